// round 2
// baseline (speedup 1.0000x reference)
#include <cuda_runtime.h>
#include <math.h>

#define TS   512
#define NB   32
#define DIN  512
#define HID  1024
#define G2   2048

__device__ float g_XG[(size_t)TS * NB * G2];
__device__ float g_XC[(size_t)TS * NB * HID];
__device__ float g_h [NB * HID];
__device__ float g_rh[NB * HID];
__device__ float g_u [NB * HID];
__device__ unsigned int g_bar;

__global__ void gru_init_kernel() {
    int idx = blockIdx.x * blockDim.x + threadIdx.x;
    if (idx < NB * HID) g_h[idx] = 0.0f;
    if (idx == 0) g_bar = 0u;
}

#define BM 128
#define BN 64
#define BK 16
#define APAD 132

__global__ void __launch_bounds__(256) sgemm_bias_kernel(
    const float* __restrict__ A, const float* __restrict__ W,
    const float* __restrict__ bias, float* __restrict__ C,
    int M, int N, int K, int ldw)
{
    __shared__ float As[BK * APAD];
    __shared__ float Ws[BK * BN];

    const int tid = threadIdx.x;
    const int tx = tid & 15;
    const int ty = tid >> 4;
    const int m0 = blockIdx.y * BM;
    const int n0 = blockIdx.x * BN;

    float acc[8][4];
#pragma unroll
    for (int i = 0; i < 8; ++i)
#pragma unroll
        for (int j = 0; j < 4; ++j) acc[i][j] = 0.0f;

    for (int k0 = 0; k0 < K; k0 += BK) {
        {
            const int kq = tid & 3;
            const int mr = tid >> 2;
#pragma unroll
            for (int it = 0; it < 2; ++it) {
                int m = mr + it * 64;
                float4 v = *(const float4*)&A[(size_t)(m0 + m) * K + k0 + kq * 4];
                As[(kq * 4 + 0) * APAD + m] = v.x;
                As[(kq * 4 + 1) * APAD + m] = v.y;
                As[(kq * 4 + 2) * APAD + m] = v.z;
                As[(kq * 4 + 3) * APAD + m] = v.w;
            }
        }
        {
            const int nq = tid & 15;
            const int kr = tid >> 4;
            float4 v = *(const float4*)&W[(size_t)(k0 + kr) * ldw + n0 + nq * 4];
            *(float4*)&Ws[kr * BN + nq * 4] = v;
        }
        __syncthreads();
#pragma unroll
        for (int kk = 0; kk < BK; ++kk) {
            float4 w4 = *(const float4*)&Ws[kk * BN + tx * 4];
            float4 a0 = *(const float4*)&As[kk * APAD + ty * 8];
            float4 a1 = *(const float4*)&As[kk * APAD + ty * 8 + 4];
            float a[8];
            a[0] = a0.x; a[1] = a0.y; a[2] = a0.z; a[3] = a0.w;
            a[4] = a1.x; a[5] = a1.y; a[6] = a1.z; a[7] = a1.w;
#pragma unroll
            for (int i = 0; i < 8; ++i) {
                acc[i][0] += a[i] * w4.x;
                acc[i][1] += a[i] * w4.y;
                acc[i][2] += a[i] * w4.z;
                acc[i][3] += a[i] * w4.w;
            }
        }
        __syncthreads();
    }

    float4 bv = *(const float4*)&bias[n0 + tx * 4];
#pragma unroll
    for (int i = 0; i < 8; ++i) {
        float4 o;
        o.x = acc[i][0] + bv.x;
        o.y = acc[i][1] + bv.y;
        o.z = acc[i][2] + bv.z;
        o.w = acc[i][3] + bv.w;
        *(float4*)&C[(size_t)(m0 + ty * 8 + i) * N + n0 + tx * 4] = o;
    }
}

#define RBLOCKS 128

__device__ __forceinline__ void grid_barrier(unsigned* expected, unsigned nb) {
    __syncthreads();
    if (threadIdx.x == 0) {
        __threadfence();
        atomicAdd(&g_bar, 1u);
        const unsigned target = *expected + nb;
        while (atomicAdd(&g_bar, 0u) < target) { }
        __threadfence();
    }
    __syncthreads();
    *expected += nb;
}

__global__ void __launch_bounds__(256, 1) gru_recurrent_kernel(
    const float* __restrict__ gk,
    const float* __restrict__ ck,
    float* __restrict__ out)
{
    __shared__ float hs[8][32][17];
    __shared__ float ws[8][16][16];
    __shared__ float red[8][512];

    const int tid  = threadIdx.x;
    const int warp = tid >> 5;
    const int lane = tid & 31;
    const int p    = blockIdx.x;
    const unsigned nb = gridDim.x;

    const int btA = lane >> 2;
    const int jtA = lane & 3;
    const int btB = lane >> 2;
    const int jtB = lane & 3;

    const float* __restrict__ Ug = gk + (size_t)DIN * G2;
    const float* __restrict__ Uc = ck + (size_t)DIN * HID;

    const int jbaseA = p * 16;
    const int jbaseB = p * 8;
    const int kbase  = warp * 128;

    unsigned expected = 0;

    for (int t = 0; t < TS; ++t) {
        // ---- Phase A: gates = sigmoid(XG + h @ Ug) ----
        float accA[4][4];
#pragma unroll
        for (int i = 0; i < 4; ++i)
#pragma unroll
            for (int j = 0; j < 4; ++j) accA[i][j] = 0.0f;

        for (int ch = 0; ch < 8; ++ch) {
            const int k0 = kbase + ch * 16;
            {
                const int kq = lane & 3;
                const int b0 = lane >> 2;
#pragma unroll
                for (int it = 0; it < 4; ++it) {
                    int b = b0 + it * 8;
                    float4 v = __ldcg((const float4*)&g_h[b * HID + k0 + kq * 4]);
                    hs[warp][b][kq * 4 + 0] = v.x;
                    hs[warp][b][kq * 4 + 1] = v.y;
                    hs[warp][b][kq * 4 + 2] = v.z;
                    hs[warp][b][kq * 4 + 3] = v.w;
                }
            }
            {
                const int jq = lane & 3;
                const int r0 = lane >> 2;
#pragma unroll
                for (int it = 0; it < 2; ++it) {
                    int r = r0 + it * 8;
                    float4 v = *(const float4*)&Ug[(size_t)(k0 + r) * G2 + jbaseA + jq * 4];
                    *(float4*)&ws[warp][r][jq * 4] = v;
                }
            }
            __syncwarp();
#pragma unroll
            for (int kk = 0; kk < 16; ++kk) {
                float4 w4 = *(const float4*)&ws[warp][kk][jtA * 4];
#pragma unroll
                for (int i = 0; i < 4; ++i) {
                    float hv = hs[warp][btA * 4 + i][kk];
                    accA[i][0] += hv * w4.x;
                    accA[i][1] += hv * w4.y;
                    accA[i][2] += hv * w4.z;
                    accA[i][3] += hv * w4.w;
                }
            }
            __syncwarp();
        }
#pragma unroll
        for (int i = 0; i < 4; ++i)
#pragma unroll
            for (int jj = 0; jj < 4; ++jj)
                red[warp][(btA * 4 + i) * 16 + jtA * 4 + jj] = accA[i][jj];
        __syncthreads();
        for (int o = tid; o < 512; o += 256) {
            float s = 0.0f;
#pragma unroll
            for (int w8 = 0; w8 < 8; ++w8) s += red[w8][o];
            const int b = o >> 4;
            const int jcol = jbaseA + (o & 15);
            const float gpre = s + g_XG[(size_t)(b * TS + t) * G2 + jcol];
            const float sg = 1.0f / (1.0f + expf(-gpre));
            if (jcol < HID) {
                float hv = __ldcg(&g_h[b * HID + jcol]);
                __stcg(&g_rh[b * HID + jcol], sg * hv);
            } else {
                __stcg(&g_u[b * HID + (jcol - HID)], sg);
            }
        }
        grid_barrier(&expected, nb);

        // ---- Phase B: c = tanh(XC + (r*h) @ Uc); h = u*h + (1-u)*c ----
        float accB[4][2];
#pragma unroll
        for (int i = 0; i < 4; ++i) { accB[i][0] = 0.0f; accB[i][1] = 0.0f; }

        for (int ch = 0; ch < 8; ++ch) {
            const int k0 = kbase + ch * 16;
            {
                const int kq = lane & 3;
                const int b0 = lane >> 2;
#pragma unroll
                for (int it = 0; it < 4; ++it) {
                    int b = b0 + it * 8;
                    float4 v = __ldcg((const float4*)&g_rh[b * HID + k0 + kq * 4]);
                    hs[warp][b][kq * 4 + 0] = v.x;
                    hs[warp][b][kq * 4 + 1] = v.y;
                    hs[warp][b][kq * 4 + 2] = v.z;
                    hs[warp][b][kq * 4 + 3] = v.w;
                }
            }
            {
                const int jq = lane & 1;
                const int r  = lane >> 1;
                float4 v = *(const float4*)&Uc[(size_t)(k0 + r) * HID + jbaseB + jq * 4];
                *(float4*)&ws[warp][r][jq * 4] = v;
            }
            __syncwarp();
#pragma unroll
            for (int kk = 0; kk < 16; ++kk) {
                float2 w2 = *(const float2*)&ws[warp][kk][jtB * 2];
#pragma unroll
                for (int i = 0; i < 4; ++i) {
                    float hv = hs[warp][btB * 4 + i][kk];
                    accB[i][0] += hv * w2.x;
                    accB[i][1] += hv * w2.y;
                }
            }
            __syncwarp();
        }
#pragma unroll
        for (int i = 0; i < 4; ++i)
#pragma unroll
            for (int jj = 0; jj < 2; ++jj)
                red[warp][(btB * 4 + i) * 8 + jtB * 2 + jj] = accB[i][jj];
        __syncthreads();
        {
            const int o = tid;
            float s = 0.0f;
#pragma unroll
            for (int w8 = 0; w8 < 8; ++w8) s += red[w8][o];
            const int b = o >> 3;
            const int jcol = jbaseB + (o & 7);
            const float c = tanhf(s + g_XC[(size_t)(b * TS + t) * HID + jcol]);
            const float u = __ldcg(&g_u[b * HID + jcol]);
            const float hv = __ldcg(&g_h[b * HID + jcol]);
            const float hn = u * hv + (1.0f - u) * c;
            __stcg(&g_h[b * HID + jcol], hn);
            out[(size_t)(b * TS + t) * HID + jcol] = hn;
        }
        grid_barrier(&expected, nb);
    }
}

extern "C" void kernel_launch(void* const* d_in, const int* in_sizes, int n_in,
                              void* d_out, int out_size) {
    const float* X  = (const float*)d_in[0];
    const float* gk = (const float*)d_in[1];
    const float* gb = (const float*)d_in[2];
    const float* ck = (const float*)d_in[3];
    const float* cb = (const float*)d_in[4];
    float* out = (float*)d_out;
    (void)in_sizes; (void)n_in; (void)out_size;

    void* pa = nullptr; void* pb = nullptr;
    cudaGetSymbolAddress(&pa, g_XG);
    cudaGetSymbolAddress(&pb, g_XC);
    float* xg_ptr = (float*)pa;
    float* xc_ptr = (float*)pb;

    gru_init_kernel<<<128, 256>>>();
    {
        dim3 grid(G2 / BN, (NB * TS) / BM);
        sgemm_bias_kernel<<<grid, 256>>>(X, gk, gb, xg_ptr, NB * TS, G2, DIN, G2);
    }
    {
        dim3 grid(HID / BN, (NB * TS) / BM);
        sgemm_bias_kernel<<<grid, 256>>>(X, ck, cb, xc_ptr, NB * TS, HID, DIN, HID);
    }
    gru_recurrent_kernel<<<RBLOCKS, 256>>>(gk, ck, out);
}

// round 3
// speedup vs baseline: 1.2594x; 1.2594x over previous
#include <cuda_runtime.h>
#include <math.h>

#define TS   512
#define NB   32
#define DIN  512
#define HID  1024
#define G2   2048

// ---------------- global scratch ----------------
__device__ float g_XG[(size_t)TS * NB * G2];
__device__ float g_XC[(size_t)TS * NB * HID];
__device__ float g_h [NB * HID];
__device__ float g_rh[NB * HID];
__device__ float g_u [NB * HID];
__device__ unsigned int g_barg[8 * 64];   // 8 group counters, padded 256B apart

__global__ void gru_init_kernel() {
    int idx = blockIdx.x * blockDim.x + threadIdx.x;
    if (idx < NB * HID) g_h[idx] = 0.0f;
    if (idx < 8 * 64) g_barg[idx] = 0u;
}

// ---------------- precompute GEMM (unchanged; ~70% fp32 peak) ----------------
#define BM 128
#define BN 64
#define BK 16
#define APAD 132

__global__ void __launch_bounds__(256) sgemm_bias_kernel(
    const float* __restrict__ A, const float* __restrict__ W,
    const float* __restrict__ bias, float* __restrict__ C,
    int M, int N, int K, int ldw)
{
    __shared__ float As[BK * APAD];
    __shared__ float Ws[BK * BN];

    const int tid = threadIdx.x;
    const int tx = tid & 15;
    const int ty = tid >> 4;
    const int m0 = blockIdx.y * BM;
    const int n0 = blockIdx.x * BN;

    float acc[8][4];
#pragma unroll
    for (int i = 0; i < 8; ++i)
#pragma unroll
        for (int j = 0; j < 4; ++j) acc[i][j] = 0.0f;

    for (int k0 = 0; k0 < K; k0 += BK) {
        {
            const int kq = tid & 3;
            const int mr = tid >> 2;
#pragma unroll
            for (int it = 0; it < 2; ++it) {
                int m = mr + it * 64;
                float4 v = *(const float4*)&A[(size_t)(m0 + m) * K + k0 + kq * 4];
                As[(kq * 4 + 0) * APAD + m] = v.x;
                As[(kq * 4 + 1) * APAD + m] = v.y;
                As[(kq * 4 + 2) * APAD + m] = v.z;
                As[(kq * 4 + 3) * APAD + m] = v.w;
            }
        }
        {
            const int nq = tid & 15;
            const int kr = tid >> 4;
            float4 v = *(const float4*)&W[(size_t)(k0 + kr) * ldw + n0 + nq * 4];
            *(float4*)&Ws[kr * BN + nq * 4] = v;
        }
        __syncthreads();
#pragma unroll
        for (int kk = 0; kk < BK; ++kk) {
            float4 w4 = *(const float4*)&Ws[kk * BN + tx * 4];
            float4 a0 = *(const float4*)&As[kk * APAD + ty * 8];
            float4 a1 = *(const float4*)&As[kk * APAD + ty * 8 + 4];
            float a[8];
            a[0] = a0.x; a[1] = a0.y; a[2] = a0.z; a[3] = a0.w;
            a[4] = a1.x; a[5] = a1.y; a[6] = a1.z; a[7] = a1.w;
#pragma unroll
            for (int i = 0; i < 8; ++i) {
                acc[i][0] += a[i] * w4.x;
                acc[i][1] += a[i] * w4.y;
                acc[i][2] += a[i] * w4.z;
                acc[i][3] += a[i] * w4.w;
            }
        }
        __syncthreads();
    }

    float4 bv = *(const float4*)&bias[n0 + tx * 4];
#pragma unroll
    for (int i = 0; i < 8; ++i) {
        float4 o;
        o.x = acc[i][0] + bv.x;
        o.y = acc[i][1] + bv.y;
        o.z = acc[i][2] + bv.z;
        o.w = acc[i][3] + bv.w;
        *(float4*)&C[(size_t)(m0 + ty * 8 + i) * N + n0 + tx * 4] = o;
    }
}

// ---------------- persistent recurrence ----------------
#define RBLOCKS  128
#define RTHREADS 512

// dynamic smem layout (floats)
#define OFF_WG   0                      // [1024][16]           16384
#define OFF_WC   16384                  // [1024][8]             8192
#define OFF_HC   24576                  // 2 x [32][129]         8256
#define HC_BUF   4128
#define OFF_RED  32832                  // max(16*544, 32*288)   9216
#define SMEM_FLOATS 42048               // 168192 bytes

__device__ __forceinline__ void grid_barrier_h(unsigned* target) {
    __syncthreads();
    if (threadIdx.x == 0) {
        __threadfence();
        atomicAdd(&g_barg[(blockIdx.x >> 4) * 64], 1u);
    }
    *target += 16;
    if (threadIdx.x < 8) {
        volatile unsigned* c = &g_barg[threadIdx.x * 64];
        while (*c < *target) { }
    }
    __threadfence();
    __syncthreads();
}

// stage chunk c of src (32 x 1024, row-major) into Hbuf[b*129 + k_local]
__device__ __forceinline__ void stage_ldg(const float* __restrict__ src, int c, float4* r) {
    const int w = threadIdx.x >> 5, lane = threadIdx.x & 31;
#pragma unroll
    for (int it = 0; it < 2; ++it) {
        int tile = w + it * 16;
        int b  = (tile & 7) * 4 + (lane >> 3);
        int kf = (tile >> 3) * 32 + (lane & 7) * 4;
        r[it] = __ldcg((const float4*)&src[b * 1024 + c * 128 + kf]);
    }
}
__device__ __forceinline__ void stage_sts(float* Hbuf, const float4* r) {
    const int w = threadIdx.x >> 5, lane = threadIdx.x & 31;
#pragma unroll
    for (int it = 0; it < 2; ++it) {
        int tile = w + it * 16;
        int b  = (tile & 7) * 4 + (lane >> 3);
        int kf = (tile >> 3) * 32 + (lane & 7) * 4;
        Hbuf[b * 129 + kf + 0] = r[it].x;
        Hbuf[b * 129 + kf + 1] = r[it].y;
        Hbuf[b * 129 + kf + 2] = r[it].z;
        Hbuf[b * 129 + kf + 3] = r[it].w;
    }
}

__global__ void __launch_bounds__(RTHREADS, 1) gru_recurrent_kernel(
    const float* __restrict__ gk,
    const float* __restrict__ ck,
    float* __restrict__ out)
{
    extern __shared__ float smem[];
    float* WgS = smem + OFF_WG;
    float* WcS = smem + OFF_WC;
    float* Hc  = smem + OFF_HC;
    float* Red = smem + OFF_RED;

    const int tid  = threadIdx.x;
    const int p    = blockIdx.x;

    const float* __restrict__ Ug = gk + (size_t)DIN * G2;
    const float* __restrict__ Uc = ck + (size_t)DIN * HID;

    const int jbaseA = p * 16;
    const int jbaseB = p * 8;

    // ---- load weight slices into SMEM once ----
#pragma unroll
    for (int it = 0; it < 8; ++it) {
        int idx = tid + it * 512;            // 0..4095
        int k = idx >> 2, j4 = idx & 3;
        float4 v = *(const float4*)&Ug[(size_t)k * G2 + jbaseA + j4 * 4];
        *(float4*)&WgS[k * 16 + j4 * 4] = v;
    }
#pragma unroll
    for (int it = 0; it < 4; ++it) {
        int idx = tid + it * 512;            // 0..2047
        int k = idx >> 1, j4 = idx & 1;
        float4 v = *(const float4*)&Uc[(size_t)k * HID + jbaseB + j4 * 4];
        *(float4*)&WcS[k * 8 + j4 * 4] = v;
    }
    __syncthreads();

    // phase A mapping: tile = tid&31 -> bt(0..7), jt(0..3); subslice sA = tid>>5 (0..15), 8 k per chunk
    const int btA = (tid & 31) >> 2;
    const int jtA = tid & 3;
    const int sA  = tid >> 5;
    // phase B mapping: tile = tid&15 -> bt(0..7), jt(0..1); subslice sB = tid>>4 (0..31), 4 k per chunk
    const int btB = (tid & 15) >> 1;
    const int jtB = tid & 1;
    const int sB  = tid >> 4;

    // epilogue A operand indices (one output per thread)
    const int bEA = tid >> 4;           // 0..31
    const int jEA = tid & 15;           // 0..15
    // epilogue B operand indices (threads 0..255)
    const int bEB = (tid & 255) >> 3;
    const int jEB = tid & 7;

    unsigned bar_target = 0;

    for (int t = 0; t < TS; ++t) {
        // =================== Phase A: gates ===================
        // prefetch epilogue operands
        float xg = __ldcg(&g_XG[((size_t)(bEA * TS + t)) * G2 + jbaseA + jEA]);
        float hvE = 0.0f;
        if (p < 64) hvE = __ldcg(&g_h[bEA * 1024 + jbaseA + jEA]);

        {
            float4 r[2];
            stage_ldg(g_h, 0, r);
            stage_sts(Hc, r);
        }
        __syncthreads();

        float acc[4][4];
#pragma unroll
        for (int i = 0; i < 4; ++i)
#pragma unroll
            for (int j = 0; j < 4; ++j) acc[i][j] = 0.0f;

        for (int c = 0; c < 8; ++c) {
            float4 r[2];
            if (c < 7) stage_ldg(g_h, c + 1, r);
            float* Hb = Hc + (c & 1) * HC_BUF;
#pragma unroll
            for (int kq = 0; kq < 8; ++kq) {
                int kl = sA * 8 + kq;
                int kg = c * 128 + kl;
                float4 w4 = *(const float4*)&WgS[kg * 16 + jtA * 4];
                float h0 = Hb[(btA * 4 + 0) * 129 + kl];
                float h1 = Hb[(btA * 4 + 1) * 129 + kl];
                float h2 = Hb[(btA * 4 + 2) * 129 + kl];
                float h3 = Hb[(btA * 4 + 3) * 129 + kl];
                acc[0][0] += h0 * w4.x; acc[0][1] += h0 * w4.y; acc[0][2] += h0 * w4.z; acc[0][3] += h0 * w4.w;
                acc[1][0] += h1 * w4.x; acc[1][1] += h1 * w4.y; acc[1][2] += h1 * w4.z; acc[1][3] += h1 * w4.w;
                acc[2][0] += h2 * w4.x; acc[2][1] += h2 * w4.y; acc[2][2] += h2 * w4.z; acc[2][3] += h2 * w4.w;
                acc[3][0] += h3 * w4.x; acc[3][1] += h3 * w4.y; acc[3][2] += h3 * w4.z; acc[3][3] += h3 * w4.w;
            }
            if (c < 7) stage_sts(Hc + ((c + 1) & 1) * HC_BUF, r);
            __syncthreads();
        }
        // reduction across 16 k-subslices
#pragma unroll
        for (int i = 0; i < 4; ++i)
#pragma unroll
            for (int jj = 0; jj < 4; ++jj)
                Red[sA * 544 + (btA * 4 + i) * 17 + jtA * 4 + jj] = acc[i][jj];
        __syncthreads();
        {
            float s = 0.0f;
#pragma unroll
            for (int ss = 0; ss < 16; ++ss) s += Red[ss * 544 + bEA * 17 + jEA];
            float sg = 1.0f / (1.0f + expf(-(s + xg)));
            if (p < 64) __stcg(&g_rh[bEA * 1024 + jbaseA + jEA], sg * hvE);
            else        __stcg(&g_u [bEA * 1024 + (jbaseA - 1024) + jEA], sg);
        }
        grid_barrier_h(&bar_target);

        // =================== Phase B: candidate + update ===================
        float xc = 0.0f, uv = 0.0f, hv = 0.0f;
        if (tid < 256) {
            xc = __ldcg(&g_XC[((size_t)(bEB * TS + t)) * HID + jbaseB + jEB]);
            uv = __ldcg(&g_u[bEB * 1024 + jbaseB + jEB]);
            hv = __ldcg(&g_h[bEB * 1024 + jbaseB + jEB]);
        }
        {
            float4 r[2];
            stage_ldg(g_rh, 0, r);
            stage_sts(Hc, r);
        }
        __syncthreads();

        float accB[4][4];
#pragma unroll
        for (int i = 0; i < 4; ++i)
#pragma unroll
            for (int j = 0; j < 4; ++j) accB[i][j] = 0.0f;

        for (int c = 0; c < 8; ++c) {
            float4 r[2];
            if (c < 7) stage_ldg(g_rh, c + 1, r);
            float* Hb = Hc + (c & 1) * HC_BUF;
#pragma unroll
            for (int kq = 0; kq < 4; ++kq) {
                int kl = sB * 4 + kq;
                int kg = c * 128 + kl;
                float4 w4 = *(const float4*)&WcS[kg * 8 + jtB * 4];
                float h0 = Hb[(btB * 4 + 0) * 129 + kl];
                float h1 = Hb[(btB * 4 + 1) * 129 + kl];
                float h2 = Hb[(btB * 4 + 2) * 129 + kl];
                float h3 = Hb[(btB * 4 + 3) * 129 + kl];
                accB[0][0] += h0 * w4.x; accB[0][1] += h0 * w4.y; accB[0][2] += h0 * w4.z; accB[0][3] += h0 * w4.w;
                accB[1][0] += h1 * w4.x; accB[1][1] += h1 * w4.y; accB[1][2] += h1 * w4.z; accB[1][3] += h1 * w4.w;
                accB[2][0] += h2 * w4.x; accB[2][1] += h2 * w4.y; accB[2][2] += h2 * w4.z; accB[2][3] += h2 * w4.w;
                accB[3][0] += h3 * w4.x; accB[3][1] += h3 * w4.y; accB[3][2] += h3 * w4.z; accB[3][3] += h3 * w4.w;
            }
            if (c < 7) stage_sts(Hc + ((c + 1) & 1) * HC_BUF, r);
            __syncthreads();
        }
#pragma unroll
        for (int i = 0; i < 4; ++i)
#pragma unroll
            for (int jj = 0; jj < 4; ++jj)
                Red[sB * 288 + (btB * 4 + i) * 9 + jtB * 4 + jj] = accB[i][jj];
        __syncthreads();
        if (tid < 256) {
            float s = 0.0f;
#pragma unroll
            for (int ss = 0; ss < 32; ++ss) s += Red[ss * 288 + bEB * 9 + jEB];
            float cc = tanhf(s + xc);
            float hn = uv * hv + (1.0f - uv) * cc;
            __stcg(&g_h[bEB * 1024 + jbaseB + jEB], hn);
            out[((size_t)bEB * TS + t) * HID + jbaseB + jEB] = hn;
        }
        grid_barrier_h(&bar_target);
    }
}

// ---------------- launch ----------------
extern "C" void kernel_launch(void* const* d_in, const int* in_sizes, int n_in,
                              void* d_out, int out_size) {
    const float* X  = (const float*)d_in[0];
    const float* gk = (const float*)d_in[1];
    const float* gb = (const float*)d_in[2];
    const float* ck = (const float*)d_in[3];
    const float* cb = (const float*)d_in[4];
    float* out = (float*)d_out;
    (void)in_sizes; (void)n_in; (void)out_size;

    void* pa = nullptr; void* pb = nullptr;
    cudaGetSymbolAddress(&pa, g_XG);
    cudaGetSymbolAddress(&pb, g_XC);
    float* xg_ptr = (float*)pa;
    float* xc_ptr = (float*)pb;

    cudaFuncSetAttribute(gru_recurrent_kernel,
                         cudaFuncAttributeMaxDynamicSharedMemorySize,
                         SMEM_FLOATS * (int)sizeof(float));

    gru_init_kernel<<<128, 256>>>();
    {
        dim3 grid(G2 / BN, (NB * TS) / BM);
        sgemm_bias_kernel<<<grid, 256>>>(X, gk, gb, xg_ptr, NB * TS, G2, DIN, G2);
    }
    {
        dim3 grid(HID / BN, (NB * TS) / BM);
        sgemm_bias_kernel<<<grid, 256>>>(X, ck, cb, xc_ptr, NB * TS, HID, DIN, HID);
    }
    gru_recurrent_kernel<<<RBLOCKS, RTHREADS, SMEM_FLOATS * sizeof(float)>>>(gk, ck, out);
}